// round 8
// baseline (speedup 1.0000x reference)
#include <cuda_runtime.h>

// RecurrentGCN_87926570483780
//
// Reference math collapses exactly:
//   - K=1 DConv: edge data is dead code.
//   - H0 = zeros -> Z,R depend only on X; cell = (1-Z)*Ht.
//   - Final op: log_softmax over a size-1 axis == 0 identically.
// Output is EXACTLY zeros([N,1]) for all inputs -> one zero-fill node.
//
// Round 8 experiment: block-size axis below 256. block=1024 regressed
// (+2.4us), suggesting per-CTA ramp scales with warps/block. Test
// 128-thread blocks at the same 123-CTA count (4 x STG.128 per thread,
// grid-strided, coalesced). If neutral, session is converged at the
// single-graph-node replay floor (~4.5us).

__global__ void __launch_bounds__(128) zero_fill_128(float4* __restrict__ out4, int n4) {
    int stride = gridDim.x * blockDim.x;            // 15744
    int i = blockIdx.x * blockDim.x + threadIdx.x;
    const float4 z = make_float4(0.f, 0.f, 0.f, 0.f);
    #pragma unroll
    for (int k = 0; k < 4; ++k) {
        int idx = i + k * stride;
        if (idx < n4) out4[idx] = z;
    }
}

extern "C" void kernel_launch(void* const* d_in, const int* in_sizes, int n_in,
                              void* d_out, int out_size) {
    (void)d_in; (void)in_sizes; (void)n_in;

    int n4 = out_size >> 2;        // 62500 (out_size % 4 == 0)
    int threads = 128;
    int blocks = 123;              // 123*128*4 = 62976 >= 62500
    zero_fill_128<<<blocks, threads>>>((float4*)d_out, n4);
}

// round 9
// speedup vs baseline: 1.0625x; 1.0625x over previous
#include <cuda_runtime.h>

// RecurrentGCN_87926570483780
//
// Reference math collapses exactly:
//   - K=1 DConv: edge data is dead code.
//   - H0 = zeros -> Z,R depend only on X; cell = (1-Z)*Ht.
//   - Final op: log_softmax over a size-1 axis == 0 identically.
// Output is EXACTLY zeros([N,1]) for all inputs -> one zero-fill node.
//
// Round 8 experiment: block-size axis below 256. block=1024 regressed
// (+2.4us), suggesting per-CTA ramp scales with warps/block. Test
// 128-thread blocks at the same 123-CTA count (4 x STG.128 per thread,
// grid-strided, coalesced). If neutral, session is converged at the
// single-graph-node replay floor (~4.5us).

__global__ void __launch_bounds__(128) zero_fill_128(float4* __restrict__ out4, int n4) {
    int stride = gridDim.x * blockDim.x;            // 15744
    int i = blockIdx.x * blockDim.x + threadIdx.x;
    const float4 z = make_float4(0.f, 0.f, 0.f, 0.f);
    #pragma unroll
    for (int k = 0; k < 4; ++k) {
        int idx = i + k * stride;
        if (idx < n4) out4[idx] = z;
    }
}

extern "C" void kernel_launch(void* const* d_in, const int* in_sizes, int n_in,
                              void* d_out, int out_size) {
    (void)d_in; (void)in_sizes; (void)n_in;

    int n4 = out_size >> 2;        // 62500 (out_size % 4 == 0)
    int threads = 128;
    int blocks = 123;              // 123*128*4 = 62976 >= 62500
    zero_fill_128<<<blocks, threads>>>((float4*)d_out, n4);
}